// round 5
// baseline (speedup 1.0000x reference)
#include <cuda_runtime.h>

// AdderNet: out[n,h,w,f] = sum_{dh,dw,c} |Xpad[n,h+dh-1,w+dw-1,c] - F[f,dh,dw,c]|
// X [8,32,32,32] f32 NHWC, F [64,3,3,32] f32, out [8,32,32,64] f32.
//
// Grid (256 nh, 2 fhalf), block 256 = wq(16) x fg(16).
// Thread: 2 pixels (w = 2wq, 2wq+1) x 2 filters (2fg, 2fg+1). f32x2 packs channel pairs.
// Filter smem stride padded to 73 float4 (1168B % 128 = 16) -> conflict-free f loads.
// X smem [dh][c4][s], s = r*17 + q with wp = 2q + r -> all 4 x loads contiguous across wq.

#define XS_F4 (3 * 8 * 34)          // 816 float4
#define FS_F4 (32 * 73)             // 2336 float4 (32 filters, padded stride 73)
#define SMEM_BYTES ((XS_F4 + FS_F4) * 16)   // 50,432 B

typedef unsigned long long u64;

__device__ __forceinline__ u64 ffma2(u64 a, u64 b, u64 c) {   // a*b + c packed
    u64 r;
    asm("fma.rn.f32x2 %0, %1, %2, %3;" : "=l"(r) : "l"(a), "l"(b), "l"(c));
    return r;
}
__device__ __forceinline__ u64 fadd2(u64 a, u64 b) {
    u64 r;
    asm("add.rn.f32x2 %0, %1, %2;" : "=l"(r) : "l"(a), "l"(b));
    return r;
}

__global__ __launch_bounds__(256, 4)
void adder_layer_kernel(const float* __restrict__ X,
                        const float* __restrict__ Fw,
                        float* __restrict__ out) {
    extern __shared__ __align__(16) float4 smem4[];
    float4* Xs4 = smem4;              // [(dh*8 + c4)*34 + s]
    float4* Fs4 = smem4 + XS_F4;      // [fl*73 + (dh*3+dw)*8 + c4]

    const int tid = threadIdx.x;
    const int nh = blockIdx.x;        // n*32 + h
    const int fbase = blockIdx.y * 32;
    const int n = nh >> 5;
    const int h = nh & 31;

    // ---- Filter fill: 32 filters of this half, padded stride 73 ----
    const float4* Fg4 = reinterpret_cast<const float4*>(Fw);
    for (int i = tid; i < 32 * 72; i += 256) {
        int fl = i / 72;
        int j = i - fl * 72;
        Fs4[fl * 73 + j] = Fg4[(fbase + fl) * 72 + j];
    }

    // ---- X fill: 3 rows, swizzled s = r*17 + q (wp = 2q + r), zero-padded ----
    const float4* Xg4 = reinterpret_cast<const float4*>(X);
    for (int i = tid; i < XS_F4; i += 256) {
        int c4 = i & 7;
        int t = i >> 3;
        int s = t % 34;
        int dh = t / 34;
        int q = s % 17, r = s / 17;
        int wp = 2 * q + r;
        int row = h - 1 + dh;
        int w = wp - 1;
        float4 v = make_float4(0.f, 0.f, 0.f, 0.f);
        if (row >= 0 && row < 32 && w >= 0 && w < 32)
            v = Xg4[(((n * 32) + row) * 32 + w) * 8 + c4];
        Xs4[(dh * 8 + c4) * 34 + s] = v;
    }
    __syncthreads();

    const int wq = tid & 15;          // pixel pair: w = 2wq, 2wq+1
    const int fg = tid >> 4;          // 0..15 -> local filters 2fg, 2fg+1

    const u64 NEG1 = 0xBF800000BF800000ULL;
    const u64 ABSM = 0x7FFFFFFF7FFFFFFFULL;

    u64 acc[2][2] = {{0ull, 0ull}, {0ull, 0ull}};   // [filter][pixel]

    const ulonglong2* Xu = reinterpret_cast<const ulonglong2*>(Xs4);
    const ulonglong2* Fu = reinterpret_cast<const ulonglong2*>(Fs4);

    #pragma unroll
    for (int dh = 0; dh < 3; dh++) {
        #pragma unroll 2
        for (int c4 = 0; c4 < 8; c4++) {
            const ulonglong2* xr = Xu + (dh * 8 + c4) * 34;
            // 4 channels each at wp = 2wq + k, k = 0..3
            ulonglong2 xv[4];
            xv[0] = xr[wq];            // wp = 2wq       (r=0, q=wq)
            xv[1] = xr[17 + wq];       // wp = 2wq+1     (r=1, q=wq)
            xv[2] = xr[wq + 1];        // wp = 2wq+2     (r=0, q=wq+1)
            xv[3] = xr[17 + wq + 1];   // wp = 2wq+3     (r=1, q=wq+1)

            #pragma unroll
            for (int fi = 0; fi < 2; fi++) {
                const ulonglong2* fr = Fu + (2 * fg + fi) * 73 + dh * 24 + c4;
                ulonglong2 tt[3];
                tt[0] = fr[0];         // dw=0
                tt[1] = fr[8];         // dw=1
                tt[2] = fr[16];        // dw=2

                #pragma unroll
                for (int p = 0; p < 2; p++) {
                    #pragma unroll
                    for (int dw = 0; dw < 3; dw++) {
                        const ulonglong2 xx = xv[p + dw];
                        acc[fi][p] = fadd2(acc[fi][p], ffma2(tt[dw].x, NEG1, xx.x) & ABSM);
                        acc[fi][p] = fadd2(acc[fi][p], ffma2(tt[dw].y, NEG1, xx.y) & ABSM);
                    }
                }
            }
        }
    }

    // ---- Epilogue: horizontal add of packed lanes, float2 store per pixel ----
    #pragma unroll
    for (int p = 0; p < 2; p++) {
        u64 a0 = acc[0][p], a1 = acc[1][p];
        float r0 = __uint_as_float((unsigned)a0) + __uint_as_float((unsigned)(a0 >> 32));
        float r1 = __uint_as_float((unsigned)a1) + __uint_as_float((unsigned)(a1 >> 32));
        *reinterpret_cast<float2*>(
            out + ((nh * 32) + 2 * wq + p) * 64 + fbase + 2 * fg) = make_float2(r0, r1);
    }
}

extern "C" void kernel_launch(void* const* d_in, const int* in_sizes, int n_in,
                              void* d_out, int out_size) {
    const float* X = (const float*)d_in[0];
    const float* Fw = (const float*)d_in[1];
    float* out = (float*)d_out;

    cudaFuncSetAttribute(adder_layer_kernel,
                         cudaFuncAttributeMaxDynamicSharedMemorySize, SMEM_BYTES);
    dim3 grid(256, 2);
    adder_layer_kernel<<<grid, 256, SMEM_BYTES>>>(X, Fw, out);
}

// round 6
// speedup vs baseline: 1.0014x; 1.0014x over previous
#include <cuda_runtime.h>

// AdderNet: out[n,h,w,f] = sum_{dh,dw,c} |Xpad[n,h+dh-1,w+dw-1,c] - F[f,dh,dw,c]|
// X [8,32,32,32] f32 NHWC, F [64,3,3,32] f32, out [8,32,32,64] f32.
//
// Grid (256 nh, 4 fquarter), block 128 = wq(16) x fg(8).
// Thread: 2 pixels x 2 filters, f32x2 packs channel pairs.
// Smem 31,744B -> 7 CTA/SM; grid 1024 ~= one balanced wave (6.7 CTA/SM).
// Software-pipelined: next-iter x prefetched, all filter taps hoisted.

#define XS_F4 (3 * 8 * 34)          // 816 float4, swizzle s = r*17+q, wp = 2q+r
#define FS_F4 (16 * 73)             // 1168 float4 (16 filters, padded stride 73)
#define SMEM_BYTES ((XS_F4 + FS_F4) * 16)   // 31,744 B

typedef unsigned long long u64;

__device__ __forceinline__ u64 ffma2(u64 a, u64 b, u64 c) {
    u64 r;
    asm("fma.rn.f32x2 %0, %1, %2, %3;" : "=l"(r) : "l"(a), "l"(b), "l"(c));
    return r;
}
__device__ __forceinline__ u64 fadd2(u64 a, u64 b) {
    u64 r;
    asm("add.rn.f32x2 %0, %1, %2;" : "=l"(r) : "l"(a), "l"(b));
    return r;
}

__global__ __launch_bounds__(128, 7)
void adder_layer_kernel(const float* __restrict__ X,
                        const float* __restrict__ Fw,
                        float* __restrict__ out) {
    extern __shared__ __align__(16) float4 smem4[];
    float4* Xs4 = smem4;              // [(dh*8 + c4)*34 + s]
    float4* Fs4 = smem4 + XS_F4;      // [fl*73 + (dh*3+dw)*8 + c4]

    const int tid = threadIdx.x;
    const int nh = blockIdx.x;        // n*32 + h
    const int fbase = blockIdx.y * 16;
    const int n = nh >> 5;
    const int h = nh & 31;

    // ---- Filter fill: 16 filters of this quarter, padded stride 73 ----
    const float4* Fg4 = reinterpret_cast<const float4*>(Fw);
    for (int i = tid; i < 16 * 72; i += 128) {
        int fl = i / 72;
        int j = i - fl * 72;
        Fs4[fl * 73 + j] = Fg4[(fbase + fl) * 72 + j];
    }

    // ---- X fill: 3 rows, swizzled s = r*17 + q (wp = 2q + r), zero-padded ----
    const float4* Xg4 = reinterpret_cast<const float4*>(X);
    for (int i = tid; i < XS_F4; i += 128) {
        int c4 = i & 7;
        int t = i >> 3;
        int s = t % 34;
        int dh = t / 34;
        int q = s % 17, r = s / 17;
        int wp = 2 * q + r;
        int row = h - 1 + dh;
        int w = wp - 1;
        float4 v = make_float4(0.f, 0.f, 0.f, 0.f);
        if (row >= 0 && row < 32 && w >= 0 && w < 32)
            v = Xg4[(((n * 32) + row) * 32 + w) * 8 + c4];
        Xs4[(dh * 8 + c4) * 34 + s] = v;
    }
    __syncthreads();

    const int wq = tid & 15;          // pixels w = 2wq, 2wq+1
    const int fg = tid >> 4;          // 0..7 -> local filters 2fg, 2fg+1

    const u64 NEG1 = 0xBF800000BF800000ULL;
    const u64 ABSM = 0x7FFFFFFF7FFFFFFFULL;

    u64 acc[2][2] = {{0ull, 0ull}, {0ull, 0ull}};   // [filter][pixel]

    const ulonglong2* Xu = reinterpret_cast<const ulonglong2*>(Xs4);
    const ulonglong2* Fu = reinterpret_cast<const ulonglong2*>(Fs4);
    const ulonglong2* Fb0 = Fu + (2 * fg) * 73;       // filter 2fg
    const ulonglong2* Fb1 = Fb0 + 73;                 // filter 2fg+1

    // x positions: wp = 2wq + k -> slots {wq, 17+wq, wq+1, 18+wq}
    ulonglong2 cur0, cur1, cur2, cur3, nxt0, nxt1, nxt2, nxt3;
    {
        const ulonglong2* xr = Xu + wq;               // kk = 0
        cur0 = xr[0]; cur1 = xr[17]; cur2 = xr[1]; cur3 = xr[18];
    }

    #pragma unroll 4
    for (int kk = 0; kk < 24; kk++) {
        // prefetch next iteration's x (clamped at the end; redundant but harmless)
        int kn = (kk < 23) ? kk + 1 : 23;
        {
            const ulonglong2* xr = Xu + kn * 34 + wq;
            nxt0 = xr[0]; nxt1 = xr[17]; nxt2 = xr[1]; nxt3 = xr[18];
        }

        const int dh = kk >> 3;
        const int c4 = kk & 7;
        const int foff = dh * 24 + c4;

        // all 6 filter taps up front (broadcast loads)
        ulonglong2 t00 = Fb0[foff];      // fi=0, dw=0
        ulonglong2 t01 = Fb0[foff + 8];
        ulonglong2 t02 = Fb0[foff + 16];
        ulonglong2 t10 = Fb1[foff];      // fi=1
        ulonglong2 t11 = Fb1[foff + 8];
        ulonglong2 t12 = Fb1[foff + 16];

        // pixel p=0 uses cur0..cur2, p=1 uses cur1..cur3
        acc[0][0] = fadd2(acc[0][0], ffma2(t00.x, NEG1, cur0.x) & ABSM);
        acc[0][0] = fadd2(acc[0][0], ffma2(t00.y, NEG1, cur0.y) & ABSM);
        acc[0][0] = fadd2(acc[0][0], ffma2(t01.x, NEG1, cur1.x) & ABSM);
        acc[0][0] = fadd2(acc[0][0], ffma2(t01.y, NEG1, cur1.y) & ABSM);
        acc[0][0] = fadd2(acc[0][0], ffma2(t02.x, NEG1, cur2.x) & ABSM);
        acc[0][0] = fadd2(acc[0][0], ffma2(t02.y, NEG1, cur2.y) & ABSM);

        acc[0][1] = fadd2(acc[0][1], ffma2(t00.x, NEG1, cur1.x) & ABSM);
        acc[0][1] = fadd2(acc[0][1], ffma2(t00.y, NEG1, cur1.y) & ABSM);
        acc[0][1] = fadd2(acc[0][1], ffma2(t01.x, NEG1, cur2.x) & ABSM);
        acc[0][1] = fadd2(acc[0][1], ffma2(t01.y, NEG1, cur2.y) & ABSM);
        acc[0][1] = fadd2(acc[0][1], ffma2(t02.x, NEG1, cur3.x) & ABSM);
        acc[0][1] = fadd2(acc[0][1], ffma2(t02.y, NEG1, cur3.y) & ABSM);

        acc[1][0] = fadd2(acc[1][0], ffma2(t10.x, NEG1, cur0.x) & ABSM);
        acc[1][0] = fadd2(acc[1][0], ffma2(t10.y, NEG1, cur0.y) & ABSM);
        acc[1][0] = fadd2(acc[1][0], ffma2(t11.x, NEG1, cur1.x) & ABSM);
        acc[1][0] = fadd2(acc[1][0], ffma2(t11.y, NEG1, cur1.y) & ABSM);
        acc[1][0] = fadd2(acc[1][0], ffma2(t12.x, NEG1, cur2.x) & ABSM);
        acc[1][0] = fadd2(acc[1][0], ffma2(t12.y, NEG1, cur2.y) & ABSM);

        acc[1][1] = fadd2(acc[1][1], ffma2(t10.x, NEG1, cur1.x) & ABSM);
        acc[1][1] = fadd2(acc[1][1], ffma2(t10.y, NEG1, cur1.y) & ABSM);
        acc[1][1] = fadd2(acc[1][1], ffma2(t11.x, NEG1, cur2.x) & ABSM);
        acc[1][1] = fadd2(acc[1][1], ffma2(t11.y, NEG1, cur2.y) & ABSM);
        acc[1][1] = fadd2(acc[1][1], ffma2(t12.x, NEG1, cur3.x) & ABSM);
        acc[1][1] = fadd2(acc[1][1], ffma2(t12.y, NEG1, cur3.y) & ABSM);

        cur0 = nxt0; cur1 = nxt1; cur2 = nxt2; cur3 = nxt3;
    }

    // ---- Epilogue: horizontal add of packed lanes, float2 store per pixel ----
    #pragma unroll
    for (int p = 0; p < 2; p++) {
        u64 a0 = acc[0][p], a1 = acc[1][p];
        float r0 = __uint_as_float((unsigned)a0) + __uint_as_float((unsigned)(a0 >> 32));
        float r1 = __uint_as_float((unsigned)a1) + __uint_as_float((unsigned)(a1 >> 32));
        *reinterpret_cast<float2*>(
            out + ((nh * 32) + 2 * wq + p) * 64 + fbase + 2 * fg) = make_float2(r0, r1);
    }
}

extern "C" void kernel_launch(void* const* d_in, const int* in_sizes, int n_in,
                              void* d_out, int out_size) {
    const float* X = (const float*)d_in[0];
    const float* Fw = (const float*)d_in[1];
    float* out = (float*)d_out;

    cudaFuncSetAttribute(adder_layer_kernel,
                         cudaFuncAttributeMaxDynamicSharedMemorySize, SMEM_BYTES);
    dim3 grid(256, 4);
    adder_layer_kernel<<<grid, 128, SMEM_BYTES>>>(X, Fw, out);
}